// round 12
// baseline (speedup 1.0000x reference)
#include <cuda_runtime.h>
#include <cuda_fp16.h>
#include <math.h>

#define B_SZ   32
#define D_IN   2
#define L_SEQ  4096
#define H_DIM  128
#define NL     6
#define NC     32
#define D_OUT  2
#define NSEQ   (B_SZ * H_DIM)        // 4096
#define CHUNKS 16
#define CHLEN  (L_SEQ / CHUNKS)      // 256
#define SPT    8
#define NG     (SPT / 2)

typedef unsigned long long u64;
typedef unsigned int u32;

// ---------------- f32x2 helpers ----------------
__device__ __forceinline__ u64 pk(float lo, float hi) {
    u64 r;
    asm("mov.b64 %0, {%1, %2};" : "=l"(r) : "r"(__float_as_uint(lo)), "r"(__float_as_uint(hi)));
    return r;
}
__device__ __forceinline__ void upk(u64 a, float& lo, float& hi) {
    u32 x, y;
    asm("mov.b64 {%0, %1}, %2;" : "=r"(x), "=r"(y) : "l"(a));
    lo = __uint_as_float(x); hi = __uint_as_float(y);
}
__device__ __forceinline__ u64 fma2(u64 a, u64 b, u64 c) {
    u64 d;
    asm("fma.rn.f32x2 %0, %1, %2, %3;" : "=l"(d) : "l"(a), "l"(b), "l"(c));
    return d;
}
__device__ __forceinline__ u64 mul2(u64 a, u64 b) {
    u64 d;
    asm("mul.rn.f32x2 %0, %1, %2;" : "=l"(d) : "l"(a), "l"(b));
    return d;
}

// ---------------- tensor-core helpers (baseline sm_103 ISA) ----------------
__device__ __forceinline__ unsigned smaddr(const void* p) {
    unsigned a;
    asm("{ .reg .u64 t; cvta.to.shared.u64 t, %1; cvt.u32.u64 %0, t; }" : "=r"(a) : "l"(p));
    return a;
}
__device__ __forceinline__ void ldm_x4(u32& r0, u32& r1, u32& r2, u32& r3, unsigned addr) {
    asm volatile("ldmatrix.sync.aligned.m8n8.x4.shared.b16 {%0,%1,%2,%3}, [%4];"
                 : "=r"(r0), "=r"(r1), "=r"(r2), "=r"(r3) : "r"(addr));
}
__device__ __forceinline__ void mma_f16(float* c, u32 a0, u32 a1, u32 a2, u32 a3,
                                        u32 b0, u32 b1) {
    asm volatile(
        "mma.sync.aligned.m16n8k16.row.col.f32.f16.f16.f32 "
        "{%0,%1,%2,%3}, {%4,%5,%6,%7}, {%8,%9}, {%0,%1,%2,%3};"
        : "+f"(c[0]), "+f"(c[1]), "+f"(c[2]), "+f"(c[3])
        : "r"(a0), "r"(a1), "r"(a2), "r"(a3), "r"(b0), "r"(b1));
}

// smem layout for glu_mma (dynamic). Pitch 272B -> conflict-free ldmatrix.
#define WPITCH 272
#define SM_W   0                    // 256 x 272 = 69632 (Wf16; zAG overlay)
#define SM_AHI 69632                // 64 x 272 = 17408
#define SM_ALO 87040                // 17408
#define SM_MV  104448               // 64 x float2
#define SMEM_MMA 104960
#define ZPITCH 132                  // floats (zAG overlay on SM_W)

#define GLT 64
#define TILES_PER_BLK 4

// ---------------- scratch ----------------
__device__ float  g_h[NSEQ * L_SEQ];
__device__ float  g_y[NSEQ * L_SEQ];
__device__ float  g_par[NL * 6 * H_DIM * NC];        // wre,wim,c2re,c2im,wpre,wpim
__device__ __half g_Wf[NL * 2 * H_DIM * H_DIM];      // fp16 weights
__device__ float  g_pooled[NSEQ];

// ---------------- parameter precompute (double; complex form) ----------------
__global__ void param_kernel(const float* __restrict__ log_dt,
                             const float* __restrict__ C_re,
                             const float* __restrict__ C_im,
                             const float* __restrict__ log_A_real,
                             const float* __restrict__ A_imag) {
    int t = blockIdx.x * blockDim.x + threadIdx.x;
    if (t >= NL * H_DIM * NC) return;
    int layer = t / (H_DIM * NC);
    int hn    = t % (H_DIM * NC);
    int h     = hn / NC;

    double dt  = exp((double)log_dt[layer * H_DIM + h]);
    double Are = -exp((double)log_A_real[t]);
    double Aim = (double)A_imag[t];
    double xre = Are * dt, xim = Aim * dt;

    double ex = exp(xre);
    double sy, cy;
    sincos(xim, &sy, &cy);
    double wre = ex * cy, wim = ex * sy;

    double em1re = ex * cy - 1.0;
    double em1im = ex * sy;

    double den = Are * Are + Aim * Aim;
    double fre = (em1re * Are + em1im * Aim) / den;
    double fim = (em1im * Are - em1re * Aim) / den;
    double cre = (double)C_re[t], cim = (double)C_im[t];
    double c2re = 2.0 * (cre * fre - cim * fim);
    double c2im = 2.0 * (cre * fim + cim * fre);

    double pre = exp(xre * (double)CHLEN);
    double ps, pc;
    sincos(xim * (double)CHLEN, &ps, &pc);

    int S = H_DIM * NC;
    int base = layer * 6 * S + hn;
    g_par[base]         = (float)wre;
    g_par[base + S]     = (float)wim;
    g_par[base + 2 * S] = (float)c2re;
    g_par[base + 3 * S] = (float)c2im;
    g_par[base + 4 * S] = (float)(pre * pc);
    g_par[base + 5 * S] = (float)(pre * ps);
}

// ---------------- weight fp16 convert ----------------
__global__ void wsplit_kernel(const float* __restrict__ out_W) {
    int t = blockIdx.x * blockDim.x + threadIdx.x;
    if (t >= NL * 2 * H_DIM * H_DIM) return;
    g_Wf[t] = __float2half_rn(out_W[t]);
}

// ---------------- encoder ----------------
__global__ void enc_kernel(const float* __restrict__ x,
                           const float* __restrict__ enc_W,
                           const float* __restrict__ enc_b) {
    int t = blockIdx.x * blockDim.x + threadIdx.x;
    if (t >= NSEQ * (L_SEQ / 4)) return;
    int l4  = t % (L_SEQ / 4);
    int seq = t / (L_SEQ / 4);
    int b = seq / H_DIM;
    int h = seq % H_DIM;
    float w0 = enc_W[h];
    float w1 = enc_W[H_DIM + h];
    float bb = enc_b[h];
    float4 a = ((const float4*)(x + (b * D_IN + 0) * L_SEQ))[l4];
    float4 c = ((const float4*)(x + (b * D_IN + 1) * L_SEQ))[l4];
    float4 r;
    r.x = fmaf(w1, c.x, fmaf(w0, a.x, bb));
    r.y = fmaf(w1, c.y, fmaf(w0, a.y, bb));
    r.z = fmaf(w1, c.z, fmaf(w0, a.z, bb));
    r.w = fmaf(w1, c.w, fmaf(w0, a.w, bb));
    ((float4*)(g_h + seq * L_SEQ))[l4] = r;
}

// ===== fused SSM: pass1 (chunk states -> smem E) + pass2 (full recurrence) =====
__global__ void __launch_bounds__(64) ssm_kernel(int layer,
                                                 const float* __restrict__ Dvec) {
    __shared__ float2 E[CHUNKS][NC];

    int t = threadIdx.x;
    int quarter = t & 3;
    int chunk   = t >> 2;
    int seq = blockIdx.x;
    int h = seq % H_DIM;

    const float* par = g_par + layer * 6 * H_DIM * NC;
    int S  = H_DIM * NC;
    int pb = h * NC + quarter * SPT;

    u64 wre2[NG], wim2[NG], nwim2[NG], sre2[NG], sim2[NG];
#pragma unroll
    for (int g = 0; g < NG; g++) {
        float2 wr = *(const float2*)(par + pb + 2 * g);
        float2 wi = *(const float2*)(par + S + pb + 2 * g);
        wre2[g]  = pk(wr.x, wr.y);
        wim2[g]  = pk(wi.x, wi.y);
        nwim2[g] = pk(-wi.x, -wi.y);
        sre2[g] = 0ull; sim2[g] = 0ull;
    }

    const float4* u4 = (const float4*)(g_h + seq * L_SEQ + chunk * CHLEN);
    for (int l = 0; l < CHLEN / 4; l++) {
        float4 u = u4[l];
        float uu[4] = {u.x, u.y, u.z, u.w};
#pragma unroll
        for (int q = 0; q < 4; q++) {
            u64 u2 = pk(uu[q], uu[q]);
#pragma unroll
            for (int g = 0; g < NG; g++) {
                u64 nr = fma2(nwim2[g], sim2[g], fma2(wre2[g], sre2[g], u2));
                u64 ni = fma2(wre2[g], sim2[g], mul2(wim2[g], sre2[g]));
                sre2[g] = nr; sim2[g] = ni;
            }
        }
    }
#pragma unroll
    for (int g = 0; g < NG; g++) {
        float r0, r1, i0, i1;
        upk(sre2[g], r0, r1);
        upk(sim2[g], i0, i1);
        E[chunk][quarter * SPT + 2 * g]     = make_float2(r0, i0);
        E[chunk][quarter * SPT + 2 * g + 1] = make_float2(r1, i1);
    }
    __syncthreads();

#pragma unroll
    for (int g = 0; g < NG; g++) { sre2[g] = 0ull; sim2[g] = 0ull; }

    if (chunk > 0) {
        u64 wpre2[NG], wpim2[NG], nwpim2[NG];
#pragma unroll
        for (int g = 0; g < NG; g++) {
            float2 wr = *(const float2*)(par + 4 * S + pb + 2 * g);
            float2 wi = *(const float2*)(par + 5 * S + pb + 2 * g);
            wpre2[g]  = pk(wr.x, wr.y);
            wpim2[g]  = pk(wi.x, wi.y);
            nwpim2[g] = pk(-wi.x, -wi.y);
        }
        for (int c = 0; c < chunk; c++) {
            const float2* Ec = &E[c][quarter * SPT];
#pragma unroll
            for (int g = 0; g < NG; g++) {
                float2 e0 = Ec[2 * g], e1 = Ec[2 * g + 1];
                u64 re2 = pk(e0.x, e1.x);
                u64 im2 = pk(e0.y, e1.y);
                u64 nr = fma2(wpre2[g], sre2[g], fma2(nwpim2[g], sim2[g], re2));
                u64 ni = fma2(wpre2[g], sim2[g], fma2(wpim2[g], sre2[g], im2));
                sre2[g] = nr; sim2[g] = ni;
            }
        }
    }

    u64 cr2[NG], nci2[NG];
#pragma unroll
    for (int g = 0; g < NG; g++) {
        float2 cr = *(const float2*)(par + 2 * S + pb + 2 * g);
        float2 ci = *(const float2*)(par + 3 * S + pb + 2 * g);
        cr2[g]  = pk(cr.x, cr.y);
        nci2[g] = pk(-ci.x, -ci.y);
    }
    float Dh = Dvec[layer * H_DIM + h];

    float* yp = g_y + seq * L_SEQ + chunk * CHLEN;

    int  q1 = quarter & 1;
    bool q2 = (quarter & 2) != 0;

    for (int l = 0; l < CHLEN / 4; l++) {
        float4 u = u4[l];
        float uu[4] = {u.x, u.y, u.z, u.w};
        float s[4];
#pragma unroll
        for (int q = 0; q < 4; q++) {
            float uv = uu[q];
            u64 u2 = pk(uv, uv);
            u64 acc2 = 0ull;
#pragma unroll
            for (int g = 0; g < NG; g++) {
                u64 nr = fma2(nwim2[g], sim2[g], fma2(wre2[g], sre2[g], u2));
                u64 ni = fma2(wre2[g], sim2[g], mul2(wim2[g], sre2[g]));
                sre2[g] = nr; sim2[g] = ni;
                acc2 = fma2(cr2[g], nr, acc2);
                acc2 = fma2(nci2[g], ni, acc2);
            }
            float alo, ahi;
            upk(acc2, alo, ahi);
            s[q] = alo + ahi;
        }
        float sA = q1 ? s[1] : s[0];
        float sB = q1 ? s[0] : s[1];
        float sC = q1 ? s[3] : s[2];
        float sD = q1 ? s[2] : s[3];
        float p0 = sA + __shfl_xor_sync(0xffffffffu, sB, 1);
        float p1 = sC + __shfl_xor_sync(0xffffffffu, sD, 1);
        float send2 = q2 ? p0 : p1;
        float tot = (q2 ? p1 : p0) + __shfl_xor_sync(0xffffffffu, send2, 2);
        float ua = q1 ? uu[1] : uu[0];
        float ub = q1 ? uu[3] : uu[2];
        float um = q2 ? ub : ua;
        float yv = fmaf(um, Dh, tot);
        float gl = 0.5f * yv * (1.f + erff(yv * 0.7071067811865476f));
        yp[4 * l + quarter] = gl;
    }
}

// ====== GLU via mma.sync fp16 2-pass split + fused GLU/residual/LN ======
__global__ void __launch_bounds__(256, 2) glu_mma_kernel(int layer,
                           const float* __restrict__ out_b,
                           const float* __restrict__ ln_g,
                           const float* __restrict__ ln_b) {
    extern __shared__ char smem[];
    unsigned sb = smaddr(smem);
    int tid = threadIdx.x;
    int w = tid >> 5, lane = tid & 31;

    int b   = blockIdx.x >> 4;
    int seg = blockIdx.x & 15;

    int mbase = (w & 3) * 16;
    int nbase = (w >> 2) * 128;
    int sel   = lane >> 3;
    int arow  = mbase + (lane & 7) + (sel & 1) * 8;
    int akadd = (sel >> 1) * 8;
    int brow0 = (lane & 7) + (sel >> 1) * 8;
    int bkadd = (sel & 1) * 8;

    const uint4* wf_g = (const uint4*)(g_Wf + layer * 2 * H_DIM * H_DIM);

    for (int tl = 0; tl < TILES_PER_BLK; tl++) {
        int l0 = seg * 256 + tl * 64;
        __syncthreads();   // previous tile's epilogue done (zAG overlay freed)

        // ---- stage Wf16 + Y hi/lo (fp16 split) ----
#pragma unroll
        for (int it = 0; it < 16; it++) {
            int idx = tid + it * 256;
            int o = idx >> 4, c = idx & 15;
            *(uint4*)(smem + SM_W + o * WPITCH + c * 16) = __ldg(wf_g + idx);
        }
#pragma unroll
        for (int it = 0; it < 16; it++) {
            int idx = tid + it * 256;
            int l = idx & 63, kp = idx >> 6;
            const float* r0 = g_y + (b * H_DIM + 2 * kp) * L_SEQ + l0;
            const float* r1 = r0 + L_SEQ;
            float f0 = __ldg(r0 + l);
            float f1 = __ldg(r1 + l);
            __half h0 = __float2half_rn(f0);
            __half h1 = __float2half_rn(f1);
            __half e0 = __float2half_rn(f0 - __half2float(h0));
            __half e1 = __float2half_rn(f1 - __half2float(h1));
            __half2 hi2 = __halves2half2(h0, h1);
            __half2 lo2 = __halves2half2(e0, e1);
            *(u32*)(smem + SM_AHI + l * WPITCH + kp * 4) = *(u32*)&hi2;
            *(u32*)(smem + SM_ALO + l * WPITCH + kp * 4) = *(u32*)&lo2;
        }
        __syncthreads();

        float acc[16][4];
#pragma unroll
        for (int n = 0; n < 16; n++)
#pragma unroll
            for (int j = 0; j < 4; j++) acc[n][j] = 0.f;

        // ---- single loop: B frags once; Ahi then Alo passes ----
#pragma unroll
        for (int ks = 0; ks < 8; ks++) {
            u32 bf[8][4];
#pragma unroll
            for (int nt2 = 0; nt2 < 8; nt2++) {
                int nrow = nbase + nt2 * 16 + brow0;
                ldm_x4(bf[nt2][0], bf[nt2][1], bf[nt2][2], bf[nt2][3],
                       sb + SM_W + nrow * WPITCH + (ks * 16 + bkadd) * 2);
            }
            u32 a0, a1, a2, a3;
            ldm_x4(a0, a1, a2, a3,
                   sb + SM_AHI + arow * WPITCH + (ks * 16 + akadd) * 2);
#pragma unroll
            for (int nt2 = 0; nt2 < 8; nt2++) {
                mma_f16(acc[2 * nt2],     a0, a1, a2, a3, bf[nt2][0], bf[nt2][1]);
                mma_f16(acc[2 * nt2 + 1], a0, a1, a2, a3, bf[nt2][2], bf[nt2][3]);
            }
            ldm_x4(a0, a1, a2, a3,
                   sb + SM_ALO + arow * WPITCH + (ks * 16 + akadd) * 2);
#pragma unroll
            for (int nt2 = 0; nt2 < 8; nt2++) {
                mma_f16(acc[2 * nt2],     a0, a1, a2, a3, bf[nt2][0], bf[nt2][1]);
                mma_f16(acc[2 * nt2 + 1], a0, a1, a2, a3, bf[nt2][2], bf[nt2][3]);
            }
        }
        __syncthreads();   // W region free -> zAG overlay

        // ---- scatter frags (+bias) to zAG (overlay SM_W) ----
        {
            float* zbase = (float*)(smem + SM_W) + (w >> 2) * GLT * ZPITCH;
            const float* ob = out_b + layer * 2 * H_DIM + nbase;
            int lrow = mbase + (lane >> 2);
            int ncol = 2 * (lane & 3);
#pragma unroll
            for (int nt = 0; nt < 16; nt++) {
                int n = nt * 8 + ncol;
                float b0 = __ldg(ob + n), b1 = __ldg(ob + n + 1);
                *(float2*)(zbase + lrow * ZPITCH + n) =
                    make_float2(acc[nt][0] + b0, acc[nt][1] + b1);
                *(float2*)(zbase + (lrow + 8) * ZPITCH + n) =
                    make_float2(acc[nt][2] + b0, acc[nt][3] + b1);
            }
        }
        __syncthreads();

        // ---- GLU + residual ----
        {
            int ch = tid & 127, lh = tid >> 7;
            float* zA = (float*)(smem + SM_W);
            float* zG = zA + GLT * ZPITCH;
            const float* hp = g_h + (b * H_DIM + ch) * L_SEQ + l0 + lh * 32;
            float hv[32];
#pragma unroll
            for (int i = 0; i < 8; i++) ((float4*)hv)[i] = __ldg((const float4*)hp + i);
#pragma unroll
            for (int i = 0; i < 32; i++) {
                int l = lh * 32 + i;
                float a = zA[l * ZPITCH + ch];
                float g = zG[l * ZPITCH + ch];
                zA[l * ZPITCH + ch] = fmaf(a, 1.f / (1.f + expf(-g)), hv[i]);
            }
        }
        __syncthreads();

        // ---- LayerNorm stats ----
        {
            float* zA = (float*)(smem + SM_W);
            float2* mv = (float2*)(smem + SM_MV);
#pragma unroll
            for (int l = w; l < GLT; l += 8) {
                float v0 = zA[l * ZPITCH + lane],      v1 = zA[l * ZPITCH + lane + 32];
                float v2 = zA[l * ZPITCH + lane + 64], v3 = zA[l * ZPITCH + lane + 96];
                float s = v0 + v1 + v2 + v3;
                float q = fmaf(v0, v0, fmaf(v1, v1, fmaf(v2, v2, v3 * v3)));
#pragma unroll
                for (int off = 16; off > 0; off >>= 1) {
                    s += __shfl_xor_sync(0xffffffffu, s, off);
                    q += __shfl_xor_sync(0xffffffffu, q, off);
                }
                if (lane == 0) {
                    float m   = s * (1.0f / H_DIM);
                    float var = q * (1.0f / H_DIM) - m * m;
                    mv[l] = make_float2(m, rsqrtf(var + 1e-5f));
                }
            }
        }
        __syncthreads();

        // ---- normalize + write back ----
        {
            int ch = tid & 127, lh = tid >> 7;
            float* zA = (float*)(smem + SM_W);
            float2* mv = (float2*)(smem + SM_MV);
            float gam = __ldg(ln_g + layer * H_DIM + ch);
            float bet = __ldg(ln_b + layer * H_DIM + ch);
            float r[32];
#pragma unroll
            for (int i = 0; i < 32; i++) {
                int l = lh * 32 + i;
                float2 m = mv[l];
                r[i] = fmaf((zA[l * ZPITCH + ch] - m.x) * m.y, gam, bet);
            }
            float4* wp = (float4*)(g_h + (b * H_DIM + ch) * L_SEQ + l0 + lh * 32);
#pragma unroll
            for (int i = 0; i < 8; i++) wp[i] = ((float4*)r)[i];
        }
    }
}

// ---------------- mean over L ----------------
__global__ void pool_kernel() {
    int seq = blockIdx.x;
    int t   = threadIdx.x;
    const float4* r = (const float4*)(g_h + seq * L_SEQ);
    float s = 0.f;
    for (int i = t; i < L_SEQ / 4; i += 256) {
        float4 v = r[i];
        s += v.x + v.y + v.z + v.w;
    }
    __shared__ float sm[256];
    sm[t] = s;
    __syncthreads();
    for (int off = 128; off > 0; off >>= 1) {
        if (t < off) sm[t] += sm[t + off];
        __syncthreads();
    }
    if (t == 0) g_pooled[seq] = sm[0] * (1.f / L_SEQ);
}

// ---------------- head ----------------
__global__ void head_kernel(const float* __restrict__ head_W,
                            const float* __restrict__ head_b,
                            float* __restrict__ out) {
    int t = threadIdx.x;
    if (t >= B_SZ * D_OUT) return;
    int b = t / D_OUT, o = t % D_OUT;
    float s = head_b[o];
    for (int h = 0; h < H_DIM; h++)
        s = fmaf(g_pooled[b * H_DIM + h], head_W[h * D_OUT + o], s);
    out[t] = s;
}

// ---------------- launch ----------------
extern "C" void kernel_launch(void* const* d_in, const int* in_sizes, int n_in,
                              void* d_out, int out_size) {
    const float* x          = (const float*)d_in[0];
    const float* enc_W      = (const float*)d_in[1];
    const float* enc_b      = (const float*)d_in[2];
    const float* log_dt     = (const float*)d_in[3];
    const float* C_re       = (const float*)d_in[4];
    const float* C_im       = (const float*)d_in[5];
    const float* log_A_real = (const float*)d_in[6];
    const float* A_imag     = (const float*)d_in[7];
    const float* Dvec       = (const float*)d_in[8];
    const float* out_W      = (const float*)d_in[9];
    const float* out_b      = (const float*)d_in[10];
    const float* ln_g       = (const float*)d_in[11];
    const float* ln_b       = (const float*)d_in[12];
    const float* head_W     = (const float*)d_in[13];
    const float* head_b     = (const float*)d_in[14];
    float* out = (float*)d_out;

    cudaFuncSetAttribute(glu_mma_kernel,
                         cudaFuncAttributeMaxDynamicSharedMemorySize, SMEM_MMA);

    param_kernel<<<(NL * H_DIM * NC + 127) / 128, 128>>>(log_dt, C_re, C_im,
                                                         log_A_real, A_imag);
    wsplit_kernel<<<(NL * 2 * H_DIM * H_DIM + 255) / 256, 256>>>(out_W);
    enc_kernel<<<(NSEQ * (L_SEQ / 4)) / 256, 256>>>(x, enc_W, enc_b);

    for (int layer = 0; layer < NL; layer++) {
        ssm_kernel<<<NSEQ, 64>>>(layer, Dvec);
        glu_mma_kernel<<<B_SZ * 16, 256, SMEM_MMA>>>(layer, out_b, ln_g, ln_b);
    }

    pool_kernel<<<NSEQ, 256>>>();
    head_kernel<<<1, 64>>>(head_W, head_b, out);
}

// round 13
// speedup vs baseline: 1.2719x; 1.2719x over previous
#include <cuda_runtime.h>
#include <cuda_fp16.h>
#include <math.h>

#define B_SZ   32
#define D_IN   2
#define L_SEQ  4096
#define H_DIM  128
#define NL     6
#define NC     32
#define D_OUT  2
#define NSEQ   (B_SZ * H_DIM)        // 4096
#define CHUNKS 16
#define CHLEN  (L_SEQ / CHUNKS)      // 256
#define SPT    8
#define NG     (SPT / 2)

typedef unsigned long long u64;
typedef unsigned int u32;

// ---------------- f32x2 helpers ----------------
__device__ __forceinline__ u64 pk(float lo, float hi) {
    u64 r;
    asm("mov.b64 %0, {%1, %2};" : "=l"(r) : "r"(__float_as_uint(lo)), "r"(__float_as_uint(hi)));
    return r;
}
__device__ __forceinline__ void upk(u64 a, float& lo, float& hi) {
    u32 x, y;
    asm("mov.b64 {%0, %1}, %2;" : "=r"(x), "=r"(y) : "l"(a));
    lo = __uint_as_float(x); hi = __uint_as_float(y);
}
__device__ __forceinline__ u64 fma2(u64 a, u64 b, u64 c) {
    u64 d;
    asm("fma.rn.f32x2 %0, %1, %2, %3;" : "=l"(d) : "l"(a), "l"(b), "l"(c));
    return d;
}
__device__ __forceinline__ u64 mul2(u64 a, u64 b) {
    u64 d;
    asm("mul.rn.f32x2 %0, %1, %2;" : "=l"(d) : "l"(a), "l"(b));
    return d;
}

// ---------------- tensor-core helpers (baseline sm_103 ISA) ----------------
__device__ __forceinline__ unsigned smaddr(const void* p) {
    unsigned a;
    asm("{ .reg .u64 t; cvta.to.shared.u64 t, %1; cvt.u32.u64 %0, t; }" : "=r"(a) : "l"(p));
    return a;
}
__device__ __forceinline__ void ldm_x4(u32& r0, u32& r1, u32& r2, u32& r3, unsigned addr) {
    asm volatile("ldmatrix.sync.aligned.m8n8.x4.shared.b16 {%0,%1,%2,%3}, [%4];"
                 : "=r"(r0), "=r"(r1), "=r"(r2), "=r"(r3) : "r"(addr));
}
__device__ __forceinline__ void mma_f16(float* c, u32 a0, u32 a1, u32 a2, u32 a3,
                                        u32 b0, u32 b1) {
    asm volatile(
        "mma.sync.aligned.m16n8k16.row.col.f32.f16.f16.f32 "
        "{%0,%1,%2,%3}, {%4,%5,%6,%7}, {%8,%9}, {%0,%1,%2,%3};"
        : "+f"(c[0]), "+f"(c[1]), "+f"(c[2]), "+f"(c[3])
        : "r"(a0), "r"(a1), "r"(a2), "r"(a3), "r"(b0), "r"(b1));
}

// smem layout for glu_mma (dynamic). Pitch 272B -> conflict-free ldmatrix.
#define WPITCH 272
#define SM_W   0                    // 256 x 272 = 69632 (Wf16; zAG overlay)
#define SM_AHI 69632                // 64 x 272 = 17408
#define SM_ALO 87040                // 17408
#define SM_MV  104448               // 64 x float2
#define SMEM_MMA 104960
#define ZPITCH 132                  // floats (zAG overlay on SM_W)

#define GLT 64
#define TILES_PER_BLK 4
#define LO_SCALE 2048.0f
#define LO_INV   (1.0f / 2048.0f)

// ---------------- scratch ----------------
__device__ float  g_h[NSEQ * L_SEQ];
__device__ float  g_y[NSEQ * L_SEQ];
__device__ float  g_par[NL * 6 * H_DIM * NC];        // wre,wim,c2re,c2im,wpre,wpim
__device__ __half g_Wf[NL * 2 * H_DIM * H_DIM];      // fp16 weights
__device__ float  g_pooled[NSEQ];

// ---------------- parameter precompute (double; complex form) ----------------
__global__ void param_kernel(const float* __restrict__ log_dt,
                             const float* __restrict__ C_re,
                             const float* __restrict__ C_im,
                             const float* __restrict__ log_A_real,
                             const float* __restrict__ A_imag) {
    int t = blockIdx.x * blockDim.x + threadIdx.x;
    if (t >= NL * H_DIM * NC) return;
    int layer = t / (H_DIM * NC);
    int hn    = t % (H_DIM * NC);
    int h     = hn / NC;

    double dt  = exp((double)log_dt[layer * H_DIM + h]);
    double Are = -exp((double)log_A_real[t]);
    double Aim = (double)A_imag[t];
    double xre = Are * dt, xim = Aim * dt;

    double ex = exp(xre);
    double sy, cy;
    sincos(xim, &sy, &cy);
    double wre = ex * cy, wim = ex * sy;

    double em1re = ex * cy - 1.0;
    double em1im = ex * sy;

    double den = Are * Are + Aim * Aim;
    double fre = (em1re * Are + em1im * Aim) / den;
    double fim = (em1im * Are - em1re * Aim) / den;
    double cre = (double)C_re[t], cim = (double)C_im[t];
    double c2re = 2.0 * (cre * fre - cim * fim);
    double c2im = 2.0 * (cre * fim + cim * fre);

    double pre = exp(xre * (double)CHLEN);
    double ps, pc;
    sincos(xim * (double)CHLEN, &ps, &pc);

    int S = H_DIM * NC;
    int base = layer * 6 * S + hn;
    g_par[base]         = (float)wre;
    g_par[base + S]     = (float)wim;
    g_par[base + 2 * S] = (float)c2re;
    g_par[base + 3 * S] = (float)c2im;
    g_par[base + 4 * S] = (float)(pre * pc);
    g_par[base + 5 * S] = (float)(pre * ps);
}

// ---------------- weight fp16 convert ----------------
__global__ void wsplit_kernel(const float* __restrict__ out_W) {
    int t = blockIdx.x * blockDim.x + threadIdx.x;
    if (t >= NL * 2 * H_DIM * H_DIM) return;
    g_Wf[t] = __float2half_rn(out_W[t]);
}

// ---------------- encoder ----------------
__global__ void enc_kernel(const float* __restrict__ x,
                           const float* __restrict__ enc_W,
                           const float* __restrict__ enc_b) {
    int t = blockIdx.x * blockDim.x + threadIdx.x;
    if (t >= NSEQ * (L_SEQ / 4)) return;
    int l4  = t % (L_SEQ / 4);
    int seq = t / (L_SEQ / 4);
    int b = seq / H_DIM;
    int h = seq % H_DIM;
    float w0 = enc_W[h];
    float w1 = enc_W[H_DIM + h];
    float bb = enc_b[h];
    float4 a = ((const float4*)(x + (b * D_IN + 0) * L_SEQ))[l4];
    float4 c = ((const float4*)(x + (b * D_IN + 1) * L_SEQ))[l4];
    float4 r;
    r.x = fmaf(w1, c.x, fmaf(w0, a.x, bb));
    r.y = fmaf(w1, c.y, fmaf(w0, a.y, bb));
    r.z = fmaf(w1, c.z, fmaf(w0, a.z, bb));
    r.w = fmaf(w1, c.w, fmaf(w0, a.w, bb));
    ((float4*)(g_h + seq * L_SEQ))[l4] = r;
}

// ===== fused SSM: pass1 (chunk states -> smem E) + pass2 (full recurrence) =====
__global__ void __launch_bounds__(64) ssm_kernel(int layer,
                                                 const float* __restrict__ Dvec) {
    __shared__ float2 E[CHUNKS][NC];

    int t = threadIdx.x;
    int quarter = t & 3;
    int chunk   = t >> 2;
    int seq = blockIdx.x;
    int h = seq % H_DIM;

    const float* par = g_par + layer * 6 * H_DIM * NC;
    int S  = H_DIM * NC;
    int pb = h * NC + quarter * SPT;

    u64 wre2[NG], wim2[NG], nwim2[NG], sre2[NG], sim2[NG];
#pragma unroll
    for (int g = 0; g < NG; g++) {
        float2 wr = *(const float2*)(par + pb + 2 * g);
        float2 wi = *(const float2*)(par + S + pb + 2 * g);
        wre2[g]  = pk(wr.x, wr.y);
        wim2[g]  = pk(wi.x, wi.y);
        nwim2[g] = pk(-wi.x, -wi.y);
        sre2[g] = 0ull; sim2[g] = 0ull;
    }

    const float4* u4 = (const float4*)(g_h + seq * L_SEQ + chunk * CHLEN);
    for (int l = 0; l < CHLEN / 4; l++) {
        float4 u = u4[l];
        float uu[4] = {u.x, u.y, u.z, u.w};
#pragma unroll
        for (int q = 0; q < 4; q++) {
            u64 u2 = pk(uu[q], uu[q]);
#pragma unroll
            for (int g = 0; g < NG; g++) {
                u64 nr = fma2(nwim2[g], sim2[g], fma2(wre2[g], sre2[g], u2));
                u64 ni = fma2(wre2[g], sim2[g], mul2(wim2[g], sre2[g]));
                sre2[g] = nr; sim2[g] = ni;
            }
        }
    }
#pragma unroll
    for (int g = 0; g < NG; g++) {
        float r0, r1, i0, i1;
        upk(sre2[g], r0, r1);
        upk(sim2[g], i0, i1);
        E[chunk][quarter * SPT + 2 * g]     = make_float2(r0, i0);
        E[chunk][quarter * SPT + 2 * g + 1] = make_float2(r1, i1);
    }
    __syncthreads();

#pragma unroll
    for (int g = 0; g < NG; g++) { sre2[g] = 0ull; sim2[g] = 0ull; }

    if (chunk > 0) {
        u64 wpre2[NG], wpim2[NG], nwpim2[NG];
#pragma unroll
        for (int g = 0; g < NG; g++) {
            float2 wr = *(const float2*)(par + 4 * S + pb + 2 * g);
            float2 wi = *(const float2*)(par + 5 * S + pb + 2 * g);
            wpre2[g]  = pk(wr.x, wr.y);
            wpim2[g]  = pk(wi.x, wi.y);
            nwpim2[g] = pk(-wi.x, -wi.y);
        }
        for (int c = 0; c < chunk; c++) {
            const float2* Ec = &E[c][quarter * SPT];
#pragma unroll
            for (int g = 0; g < NG; g++) {
                float2 e0 = Ec[2 * g], e1 = Ec[2 * g + 1];
                u64 re2 = pk(e0.x, e1.x);
                u64 im2 = pk(e0.y, e1.y);
                u64 nr = fma2(wpre2[g], sre2[g], fma2(nwpim2[g], sim2[g], re2));
                u64 ni = fma2(wpre2[g], sim2[g], fma2(wpim2[g], sre2[g], im2));
                sre2[g] = nr; sim2[g] = ni;
            }
        }
    }

    u64 cr2[NG], nci2[NG];
#pragma unroll
    for (int g = 0; g < NG; g++) {
        float2 cr = *(const float2*)(par + 2 * S + pb + 2 * g);
        float2 ci = *(const float2*)(par + 3 * S + pb + 2 * g);
        cr2[g]  = pk(cr.x, cr.y);
        nci2[g] = pk(-ci.x, -ci.y);
    }
    float Dh = Dvec[layer * H_DIM + h];

    float* yp = g_y + seq * L_SEQ + chunk * CHLEN;

    int  q1 = quarter & 1;
    bool q2 = (quarter & 2) != 0;

    for (int l = 0; l < CHLEN / 4; l++) {
        float4 u = u4[l];
        float uu[4] = {u.x, u.y, u.z, u.w};
        float s[4];
#pragma unroll
        for (int q = 0; q < 4; q++) {
            float uv = uu[q];
            u64 u2 = pk(uv, uv);
            u64 acc2 = 0ull;
#pragma unroll
            for (int g = 0; g < NG; g++) {
                u64 nr = fma2(nwim2[g], sim2[g], fma2(wre2[g], sre2[g], u2));
                u64 ni = fma2(wre2[g], sim2[g], mul2(wim2[g], sre2[g]));
                sre2[g] = nr; sim2[g] = ni;
                acc2 = fma2(cr2[g], nr, acc2);
                acc2 = fma2(nci2[g], ni, acc2);
            }
            float alo, ahi;
            upk(acc2, alo, ahi);
            s[q] = alo + ahi;
        }
        float sA = q1 ? s[1] : s[0];
        float sB = q1 ? s[0] : s[1];
        float sC = q1 ? s[3] : s[2];
        float sD = q1 ? s[2] : s[3];
        float p0 = sA + __shfl_xor_sync(0xffffffffu, sB, 1);
        float p1 = sC + __shfl_xor_sync(0xffffffffu, sD, 1);
        float send2 = q2 ? p0 : p1;
        float tot = (q2 ? p1 : p0) + __shfl_xor_sync(0xffffffffu, send2, 2);
        float ua = q1 ? uu[1] : uu[0];
        float ub = q1 ? uu[3] : uu[2];
        float um = q2 ? ub : ua;
        float yv = fmaf(um, Dh, tot);
        float gl = 0.5f * yv * (1.f + erff(yv * 0.7071067811865476f));
        yp[4 * l + quarter] = gl;
    }
}

// ====== GLU via mma.sync fp16 2-pass split (lo pass scaled, no denormals) ======
__global__ void __launch_bounds__(256, 2) glu_mma_kernel(int layer,
                           const float* __restrict__ out_b,
                           const float* __restrict__ ln_g,
                           const float* __restrict__ ln_b) {
    extern __shared__ char smem[];
    unsigned sb = smaddr(smem);
    int tid = threadIdx.x;
    int w = tid >> 5, lane = tid & 31;

    int b   = blockIdx.x >> 4;
    int seg = blockIdx.x & 15;

    int mbase = (w & 3) * 16;
    int nbase = (w >> 2) * 128;
    int sel   = lane >> 3;
    int arow  = mbase + (lane & 7) + (sel & 1) * 8;
    int akadd = (sel >> 1) * 8;
    int brow0 = (lane & 7) + (sel >> 1) * 8;
    int bkadd = (sel & 1) * 8;

    const uint4* wf_g = (const uint4*)(g_Wf + layer * 2 * H_DIM * H_DIM);

    for (int tl = 0; tl < TILES_PER_BLK; tl++) {
        int l0 = seg * 256 + tl * 64;
        __syncthreads();   // previous tile's epilogue done (zAG overlay freed)

        // ---- stage Wf16 + Y hi/lo (lo scaled by 2048 -> normal fp16 range) ----
#pragma unroll
        for (int it = 0; it < 16; it++) {
            int idx = tid + it * 256;
            int o = idx >> 4, c = idx & 15;
            *(uint4*)(smem + SM_W + o * WPITCH + c * 16) = __ldg(wf_g + idx);
        }
#pragma unroll
        for (int it = 0; it < 16; it++) {
            int idx = tid + it * 256;
            int l = idx & 63, kp = idx >> 6;
            const float* r0 = g_y + (b * H_DIM + 2 * kp) * L_SEQ + l0;
            const float* r1 = r0 + L_SEQ;
            float f0 = __ldg(r0 + l);
            float f1 = __ldg(r1 + l);
            __half h0 = __float2half_rn(f0);
            __half h1 = __float2half_rn(f1);
            __half e0 = __float2half_rn((f0 - __half2float(h0)) * LO_SCALE);
            __half e1 = __float2half_rn((f1 - __half2float(h1)) * LO_SCALE);
            __half2 hi2 = __halves2half2(h0, h1);
            __half2 lo2 = __halves2half2(e0, e1);
            *(u32*)(smem + SM_AHI + l * WPITCH + kp * 4) = *(u32*)&hi2;
            *(u32*)(smem + SM_ALO + l * WPITCH + kp * 4) = *(u32*)&lo2;
        }
        __syncthreads();

        float acc[16][4];
#pragma unroll
        for (int n = 0; n < 16; n++)
#pragma unroll
            for (int j = 0; j < 4; j++) acc[n][j] = 0.f;

        // ---- pass 1: Alo' x W (scaled lo residuals) ----
#pragma unroll
        for (int ks = 0; ks < 8; ks++) {
            u32 a0, a1, a2, a3;
            ldm_x4(a0, a1, a2, a3,
                   sb + SM_ALO + arow * WPITCH + (ks * 16 + akadd) * 2);
#pragma unroll
            for (int nt2 = 0; nt2 < 8; nt2++) {
                u32 b0, b1, b2, b3;
                int nrow = nbase + nt2 * 16 + brow0;
                ldm_x4(b0, b1, b2, b3,
                       sb + SM_W + nrow * WPITCH + (ks * 16 + bkadd) * 2);
                mma_f16(acc[2 * nt2],     a0, a1, a2, a3, b0, b1);
                mma_f16(acc[2 * nt2 + 1], a0, a1, a2, a3, b2, b3);
            }
        }

        // rescale lo contribution
#pragma unroll
        for (int n = 0; n < 16; n++)
#pragma unroll
            for (int j = 0; j < 4; j++) acc[n][j] *= LO_INV;

        // ---- pass 2: Ahi x W ----
#pragma unroll
        for (int ks = 0; ks < 8; ks++) {
            u32 a0, a1, a2, a3;
            ldm_x4(a0, a1, a2, a3,
                   sb + SM_AHI + arow * WPITCH + (ks * 16 + akadd) * 2);
#pragma unroll
            for (int nt2 = 0; nt2 < 8; nt2++) {
                u32 b0, b1, b2, b3;
                int nrow = nbase + nt2 * 16 + brow0;
                ldm_x4(b0, b1, b2, b3,
                       sb + SM_W + nrow * WPITCH + (ks * 16 + bkadd) * 2);
                mma_f16(acc[2 * nt2],     a0, a1, a2, a3, b0, b1);
                mma_f16(acc[2 * nt2 + 1], a0, a1, a2, a3, b2, b3);
            }
        }
        __syncthreads();   // W region free -> zAG overlay

        // ---- scatter frags (+bias) to zAG (overlay SM_W) ----
        {
            float* zbase = (float*)(smem + SM_W) + (w >> 2) * GLT * ZPITCH;
            const float* ob = out_b + layer * 2 * H_DIM + nbase;
            int lrow = mbase + (lane >> 2);
            int ncol = 2 * (lane & 3);
#pragma unroll
            for (int nt = 0; nt < 16; nt++) {
                int n = nt * 8 + ncol;
                float b0 = __ldg(ob + n), b1 = __ldg(ob + n + 1);
                *(float2*)(zbase + lrow * ZPITCH + n) =
                    make_float2(acc[nt][0] + b0, acc[nt][1] + b1);
                *(float2*)(zbase + (lrow + 8) * ZPITCH + n) =
                    make_float2(acc[nt][2] + b0, acc[nt][3] + b1);
            }
        }
        __syncthreads();

        // ---- GLU + residual ----
        {
            int ch = tid & 127, lh = tid >> 7;
            float* zA = (float*)(smem + SM_W);
            float* zG = zA + GLT * ZPITCH;
            const float* hp = g_h + (b * H_DIM + ch) * L_SEQ + l0 + lh * 32;
            float hv[32];
#pragma unroll
            for (int i = 0; i < 8; i++) ((float4*)hv)[i] = __ldg((const float4*)hp + i);
#pragma unroll
            for (int i = 0; i < 32; i++) {
                int l = lh * 32 + i;
                float a = zA[l * ZPITCH + ch];
                float g = zG[l * ZPITCH + ch];
                zA[l * ZPITCH + ch] = fmaf(a, 1.f / (1.f + expf(-g)), hv[i]);
            }
        }
        __syncthreads();

        // ---- LayerNorm stats ----
        {
            float* zA = (float*)(smem + SM_W);
            float2* mv = (float2*)(smem + SM_MV);
#pragma unroll
            for (int l = w; l < GLT; l += 8) {
                float v0 = zA[l * ZPITCH + lane],      v1 = zA[l * ZPITCH + lane + 32];
                float v2 = zA[l * ZPITCH + lane + 64], v3 = zA[l * ZPITCH + lane + 96];
                float s = v0 + v1 + v2 + v3;
                float q = fmaf(v0, v0, fmaf(v1, v1, fmaf(v2, v2, v3 * v3)));
#pragma unroll
                for (int off = 16; off > 0; off >>= 1) {
                    s += __shfl_xor_sync(0xffffffffu, s, off);
                    q += __shfl_xor_sync(0xffffffffu, q, off);
                }
                if (lane == 0) {
                    float m   = s * (1.0f / H_DIM);
                    float var = q * (1.0f / H_DIM) - m * m;
                    mv[l] = make_float2(m, rsqrtf(var + 1e-5f));
                }
            }
        }
        __syncthreads();

        // ---- normalize + write back ----
        {
            int ch = tid & 127, lh = tid >> 7;
            float* zA = (float*)(smem + SM_W);
            float2* mv = (float2*)(smem + SM_MV);
            float gam = __ldg(ln_g + layer * H_DIM + ch);
            float bet = __ldg(ln_b + layer * H_DIM + ch);
            float r[32];
#pragma unroll
            for (int i = 0; i < 32; i++) {
                int l = lh * 32 + i;
                float2 m = mv[l];
                r[i] = fmaf((zA[l * ZPITCH + ch] - m.x) * m.y, gam, bet);
            }
            float4* wp = (float4*)(g_h + (b * H_DIM + ch) * L_SEQ + l0 + lh * 32);
#pragma unroll
            for (int i = 0; i < 8; i++) wp[i] = ((float4*)r)[i];
        }
    }
}

// ---------------- mean over L ----------------
__global__ void pool_kernel() {
    int seq = blockIdx.x;
    int t   = threadIdx.x;
    const float4* r = (const float4*)(g_h + seq * L_SEQ);
    float s = 0.f;
    for (int i = t; i < L_SEQ / 4; i += 256) {
        float4 v = r[i];
        s += v.x + v.y + v.z + v.w;
    }
    __shared__ float sm[256];
    sm[t] = s;
    __syncthreads();
    for (int off = 128; off > 0; off >>= 1) {
        if (t < off) sm[t] += sm[t + off];
        __syncthreads();
    }
    if (t == 0) g_pooled[seq] = sm[0] * (1.f / L_SEQ);
}

// ---------------- head ----------------
__global__ void head_kernel(const float* __restrict__ head_W,
                            const float* __restrict__ head_b,
                            float* __restrict__ out) {
    int t = threadIdx.x;
    if (t >= B_SZ * D_OUT) return;
    int b = t / D_OUT, o = t % D_OUT;
    float s = head_b[o];
    for (int h = 0; h < H_DIM; h++)
        s = fmaf(g_pooled[b * H_DIM + h], head_W[h * D_OUT + o], s);
    out[t] = s;
}

// ---------------- launch ----------------
extern "C" void kernel_launch(void* const* d_in, const int* in_sizes, int n_in,
                              void* d_out, int out_size) {
    const float* x          = (const float*)d_in[0];
    const float* enc_W      = (const float*)d_in[1];
    const float* enc_b      = (const float*)d_in[2];
    const float* log_dt     = (const float*)d_in[3];
    const float* C_re       = (const float*)d_in[4];
    const float* C_im       = (const float*)d_in[5];
    const float* log_A_real = (const float*)d_in[6];
    const float* A_imag     = (const float*)d_in[7];
    const float* Dvec       = (const float*)d_in[8];
    const float* out_W      = (const float*)d_in[9];
    const float* out_b      = (const float*)d_in[10];
    const float* ln_g       = (const float*)d_in[11];
    const float* ln_b       = (const float*)d_in[12];
    const float* head_W     = (const float*)d_in[13];
    const float* head_b     = (const float*)d_in[14];
    float* out = (float*)d_out;

    cudaFuncSetAttribute(glu_mma_kernel,
                         cudaFuncAttributeMaxDynamicSharedMemorySize, SMEM_MMA);

    param_kernel<<<(NL * H_DIM * NC + 127) / 128, 128>>>(log_dt, C_re, C_im,
                                                         log_A_real, A_imag);
    wsplit_kernel<<<(NL * 2 * H_DIM * H_DIM + 255) / 256, 256>>>(out_W);
    enc_kernel<<<(NSEQ * (L_SEQ / 4)) / 256, 256>>>(x, enc_W, enc_b);

    for (int layer = 0; layer < NL; layer++) {
        ssm_kernel<<<NSEQ, 64>>>(layer, Dvec);
        glu_mma_kernel<<<B_SZ * 16, 256, SMEM_MMA>>>(layer, out_b, ln_g, ln_b);
    }

    pool_kernel<<<NSEQ, 256>>>();
    head_kernel<<<1, 64>>>(head_W, head_b, out);
}

// round 14
// speedup vs baseline: 1.5593x; 1.2259x over previous
#include <cuda_runtime.h>
#include <cuda_fp16.h>
#include <math.h>

#define B_SZ   32
#define D_IN   2
#define L_SEQ  4096
#define H_DIM  128
#define NL     6
#define NC     32
#define D_OUT  2
#define NSEQ   (B_SZ * H_DIM)        // 4096
#define CHUNKS 16
#define CHLEN  (L_SEQ / CHUNKS)      // 256
#define SPT    8
#define NG     (SPT / 2)

typedef unsigned long long u64;
typedef unsigned int u32;

// ---------------- f32x2 helpers ----------------
__device__ __forceinline__ u64 pk(float lo, float hi) {
    u64 r;
    asm("mov.b64 %0, {%1, %2};" : "=l"(r) : "r"(__float_as_uint(lo)), "r"(__float_as_uint(hi)));
    return r;
}
__device__ __forceinline__ void upk(u64 a, float& lo, float& hi) {
    u32 x, y;
    asm("mov.b64 {%0, %1}, %2;" : "=r"(x), "=r"(y) : "l"(a));
    lo = __uint_as_float(x); hi = __uint_as_float(y);
}
__device__ __forceinline__ u64 fma2(u64 a, u64 b, u64 c) {
    u64 d;
    asm("fma.rn.f32x2 %0, %1, %2, %3;" : "=l"(d) : "l"(a), "l"(b), "l"(c));
    return d;
}
__device__ __forceinline__ u64 mul2(u64 a, u64 b) {
    u64 d;
    asm("mul.rn.f32x2 %0, %1, %2;" : "=l"(d) : "l"(a), "l"(b));
    return d;
}

// ---------------- tensor-core helpers (baseline sm_103 ISA) ----------------
__device__ __forceinline__ unsigned smaddr(const void* p) {
    unsigned a;
    asm("{ .reg .u64 t; cvta.to.shared.u64 t, %1; cvt.u32.u64 %0, t; }" : "=r"(a) : "l"(p));
    return a;
}
__device__ __forceinline__ void ldm_x4(u32& r0, u32& r1, u32& r2, u32& r3, unsigned addr) {
    asm volatile("ldmatrix.sync.aligned.m8n8.x4.shared.b16 {%0,%1,%2,%3}, [%4];"
                 : "=r"(r0), "=r"(r1), "=r"(r2), "=r"(r3) : "r"(addr));
}
__device__ __forceinline__ void mma_f16(float* c, u32 a0, u32 a1, u32 a2, u32 a3,
                                        u32 b0, u32 b1) {
    asm volatile(
        "mma.sync.aligned.m16n8k16.row.col.f32.f16.f16.f32 "
        "{%0,%1,%2,%3}, {%4,%5,%6,%7}, {%8,%9}, {%0,%1,%2,%3};"
        : "+f"(c[0]), "+f"(c[1]), "+f"(c[2]), "+f"(c[3])
        : "r"(a0), "r"(a1), "r"(a2), "r"(a3), "r"(b0), "r"(b1));
}

// smem layout for glu_mma (dynamic). Pitch 272B -> conflict-free ldmatrix.
#define WPITCH 272
#define SM_W   0                    // 256 x 272 = 69632 (Wf16; zAG overlay)
#define SM_AHI 69632                // 64 x 272 = 17408
#define SM_ALO 87040                // 17408
#define SM_MV  104448               // 64 x float2
#define SMEM_MMA 104960
#define ZPITCH 132                  // floats (zAG overlay on SM_W)

#define GLT 64
#define TILES_PER_BLK 4

// ---------------- scratch ----------------
__device__ float  g_h[NSEQ * L_SEQ];
__device__ float  g_y[NSEQ * L_SEQ];
__device__ float  g_par[NL * 6 * H_DIM * NC];        // wre,wim,c2re,c2im,wpre,wpim
__device__ __half g_Wf[NL * 2 * H_DIM * H_DIM];      // fp16 weights
__device__ float  g_pooled[NSEQ];

// ---------------- parameter precompute (double; complex form) ----------------
__global__ void param_kernel(const float* __restrict__ log_dt,
                             const float* __restrict__ C_re,
                             const float* __restrict__ C_im,
                             const float* __restrict__ log_A_real,
                             const float* __restrict__ A_imag) {
    int t = blockIdx.x * blockDim.x + threadIdx.x;
    if (t >= NL * H_DIM * NC) return;
    int layer = t / (H_DIM * NC);
    int hn    = t % (H_DIM * NC);
    int h     = hn / NC;

    double dt  = exp((double)log_dt[layer * H_DIM + h]);
    double Are = -exp((double)log_A_real[t]);
    double Aim = (double)A_imag[t];
    double xre = Are * dt, xim = Aim * dt;

    double ex = exp(xre);
    double sy, cy;
    sincos(xim, &sy, &cy);
    double wre = ex * cy, wim = ex * sy;

    double em1re = ex * cy - 1.0;
    double em1im = ex * sy;

    double den = Are * Are + Aim * Aim;
    double fre = (em1re * Are + em1im * Aim) / den;
    double fim = (em1im * Are - em1re * Aim) / den;
    double cre = (double)C_re[t], cim = (double)C_im[t];
    double c2re = 2.0 * (cre * fre - cim * fim);
    double c2im = 2.0 * (cre * fim + cim * fre);

    double pre = exp(xre * (double)CHLEN);
    double ps, pc;
    sincos(xim * (double)CHLEN, &ps, &pc);

    int S = H_DIM * NC;
    int base = layer * 6 * S + hn;
    g_par[base]         = (float)wre;
    g_par[base + S]     = (float)wim;
    g_par[base + 2 * S] = (float)c2re;
    g_par[base + 3 * S] = (float)c2im;
    g_par[base + 4 * S] = (float)(pre * pc);
    g_par[base + 5 * S] = (float)(pre * ps);
}

// ---------------- weight fp16 convert ----------------
__global__ void wsplit_kernel(const float* __restrict__ out_W) {
    int t = blockIdx.x * blockDim.x + threadIdx.x;
    if (t >= NL * 2 * H_DIM * H_DIM) return;
    g_Wf[t] = __float2half_rn(out_W[t]);
}

// ---------------- encoder ----------------
__global__ void enc_kernel(const float* __restrict__ x,
                           const float* __restrict__ enc_W,
                           const float* __restrict__ enc_b) {
    int t = blockIdx.x * blockDim.x + threadIdx.x;
    if (t >= NSEQ * (L_SEQ / 4)) return;
    int l4  = t % (L_SEQ / 4);
    int seq = t / (L_SEQ / 4);
    int b = seq / H_DIM;
    int h = seq % H_DIM;
    float w0 = enc_W[h];
    float w1 = enc_W[H_DIM + h];
    float bb = enc_b[h];
    float4 a = ((const float4*)(x + (b * D_IN + 0) * L_SEQ))[l4];
    float4 c = ((const float4*)(x + (b * D_IN + 1) * L_SEQ))[l4];
    float4 r;
    r.x = fmaf(w1, c.x, fmaf(w0, a.x, bb));
    r.y = fmaf(w1, c.y, fmaf(w0, a.y, bb));
    r.z = fmaf(w1, c.z, fmaf(w0, a.z, bb));
    r.w = fmaf(w1, c.w, fmaf(w0, a.w, bb));
    ((float4*)(g_h + seq * L_SEQ))[l4] = r;
}

// ===== fused SSM: pass1 (chunk states -> smem E) + pass2 (full recurrence) =====
__global__ void __launch_bounds__(64) ssm_kernel(int layer,
                                                 const float* __restrict__ Dvec) {
    __shared__ float2 E[CHUNKS][NC];

    int t = threadIdx.x;
    int quarter = t & 3;
    int chunk   = t >> 2;
    int seq = blockIdx.x;
    int h = seq % H_DIM;

    const float* par = g_par + layer * 6 * H_DIM * NC;
    int S  = H_DIM * NC;
    int pb = h * NC + quarter * SPT;

    u64 wre2[NG], wim2[NG], nwim2[NG], sre2[NG], sim2[NG];
#pragma unroll
    for (int g = 0; g < NG; g++) {
        float2 wr = *(const float2*)(par + pb + 2 * g);
        float2 wi = *(const float2*)(par + S + pb + 2 * g);
        wre2[g]  = pk(wr.x, wr.y);
        wim2[g]  = pk(wi.x, wi.y);
        nwim2[g] = pk(-wi.x, -wi.y);
        sre2[g] = 0ull; sim2[g] = 0ull;
    }

    const float4* u4 = (const float4*)(g_h + seq * L_SEQ + chunk * CHLEN);
    for (int l = 0; l < CHLEN / 4; l++) {
        float4 u = u4[l];
        float uu[4] = {u.x, u.y, u.z, u.w};
#pragma unroll
        for (int q = 0; q < 4; q++) {
            u64 u2 = pk(uu[q], uu[q]);
#pragma unroll
            for (int g = 0; g < NG; g++) {
                u64 nr = fma2(nwim2[g], sim2[g], fma2(wre2[g], sre2[g], u2));
                u64 ni = fma2(wre2[g], sim2[g], mul2(wim2[g], sre2[g]));
                sre2[g] = nr; sim2[g] = ni;
            }
        }
    }
#pragma unroll
    for (int g = 0; g < NG; g++) {
        float r0, r1, i0, i1;
        upk(sre2[g], r0, r1);
        upk(sim2[g], i0, i1);
        E[chunk][quarter * SPT + 2 * g]     = make_float2(r0, i0);
        E[chunk][quarter * SPT + 2 * g + 1] = make_float2(r1, i1);
    }
    __syncthreads();

#pragma unroll
    for (int g = 0; g < NG; g++) { sre2[g] = 0ull; sim2[g] = 0ull; }

    if (chunk > 0) {
        u64 wpre2[NG], wpim2[NG], nwpim2[NG];
#pragma unroll
        for (int g = 0; g < NG; g++) {
            float2 wr = *(const float2*)(par + 4 * S + pb + 2 * g);
            float2 wi = *(const float2*)(par + 5 * S + pb + 2 * g);
            wpre2[g]  = pk(wr.x, wr.y);
            wpim2[g]  = pk(wi.x, wi.y);
            nwpim2[g] = pk(-wi.x, -wi.y);
        }
        for (int c = 0; c < chunk; c++) {
            const float2* Ec = &E[c][quarter * SPT];
#pragma unroll
            for (int g = 0; g < NG; g++) {
                float2 e0 = Ec[2 * g], e1 = Ec[2 * g + 1];
                u64 re2 = pk(e0.x, e1.x);
                u64 im2 = pk(e0.y, e1.y);
                u64 nr = fma2(wpre2[g], sre2[g], fma2(nwpim2[g], sim2[g], re2));
                u64 ni = fma2(wpre2[g], sim2[g], fma2(wpim2[g], sre2[g], im2));
                sre2[g] = nr; sim2[g] = ni;
            }
        }
    }

    u64 cr2[NG], nci2[NG];
#pragma unroll
    for (int g = 0; g < NG; g++) {
        float2 cr = *(const float2*)(par + 2 * S + pb + 2 * g);
        float2 ci = *(const float2*)(par + 3 * S + pb + 2 * g);
        cr2[g]  = pk(cr.x, cr.y);
        nci2[g] = pk(-ci.x, -ci.y);
    }
    float Dh = Dvec[layer * H_DIM + h];

    float* yp = g_y + seq * L_SEQ + chunk * CHLEN;

    int  q1 = quarter & 1;
    bool q2 = (quarter & 2) != 0;

    for (int l = 0; l < CHLEN / 4; l++) {
        float4 u = u4[l];
        float uu[4] = {u.x, u.y, u.z, u.w};
        float s[4];
#pragma unroll
        for (int q = 0; q < 4; q++) {
            float uv = uu[q];
            u64 u2 = pk(uv, uv);
            u64 acc2 = 0ull;
#pragma unroll
            for (int g = 0; g < NG; g++) {
                u64 nr = fma2(nwim2[g], sim2[g], fma2(wre2[g], sre2[g], u2));
                u64 ni = fma2(wre2[g], sim2[g], mul2(wim2[g], sre2[g]));
                sre2[g] = nr; sim2[g] = ni;
                acc2 = fma2(cr2[g], nr, acc2);
                acc2 = fma2(nci2[g], ni, acc2);
            }
            float alo, ahi;
            upk(acc2, alo, ahi);
            s[q] = alo + ahi;
        }
        float sA = q1 ? s[1] : s[0];
        float sB = q1 ? s[0] : s[1];
        float sC = q1 ? s[3] : s[2];
        float sD = q1 ? s[2] : s[3];
        float p0 = sA + __shfl_xor_sync(0xffffffffu, sB, 1);
        float p1 = sC + __shfl_xor_sync(0xffffffffu, sD, 1);
        float send2 = q2 ? p0 : p1;
        float tot = (q2 ? p1 : p0) + __shfl_xor_sync(0xffffffffu, send2, 2);
        float ua = q1 ? uu[1] : uu[0];
        float ub = q1 ? uu[3] : uu[2];
        float um = q2 ? ub : ua;
        float yv = fmaf(um, Dh, tot);
        float gl = 0.5f * yv * (1.f + erff(yv * 0.7071067811865476f));
        yp[4 * l + quarter] = gl;
    }
}

// ====== GLU via mma.sync fp16 2-pass split, shared B fragments per ks ======
__global__ void __launch_bounds__(256, 2) glu_mma_kernel(int layer,
                           const float* __restrict__ out_b,
                           const float* __restrict__ ln_g,
                           const float* __restrict__ ln_b) {
    extern __shared__ char smem[];
    unsigned sb = smaddr(smem);
    int tid = threadIdx.x;
    int w = tid >> 5, lane = tid & 31;

    int b   = blockIdx.x >> 4;
    int seg = blockIdx.x & 15;

    int mbase = (w & 3) * 16;
    int nbase = (w >> 2) * 128;
    int sel   = lane >> 3;
    int arow  = mbase + (lane & 7) + (sel & 1) * 8;
    int akadd = (sel >> 1) * 8;
    int brow0 = (lane & 7) + (sel >> 1) * 8;
    int bkadd = (sel & 1) * 8;

    const uint4* wf_g = (const uint4*)(g_Wf + layer * 2 * H_DIM * H_DIM);

    for (int tl = 0; tl < TILES_PER_BLK; tl++) {
        int l0 = seg * 256 + tl * 64;
        __syncthreads();   // previous tile's epilogue done (zAG overlay freed)

        // ---- stage Wf16 + Y hi/lo (fp16 split) ----
#pragma unroll
        for (int it = 0; it < 16; it++) {
            int idx = tid + it * 256;
            int o = idx >> 4, c = idx & 15;
            *(uint4*)(smem + SM_W + o * WPITCH + c * 16) = __ldg(wf_g + idx);
        }
#pragma unroll
        for (int it = 0; it < 16; it++) {
            int idx = tid + it * 256;
            int l = idx & 63, kp = idx >> 6;
            const float* r0 = g_y + (b * H_DIM + 2 * kp) * L_SEQ + l0;
            const float* r1 = r0 + L_SEQ;
            float f0 = __ldg(r0 + l);
            float f1 = __ldg(r1 + l);
            __half h0 = __float2half_rn(f0);
            __half h1 = __float2half_rn(f1);
            __half e0 = __float2half_rn(f0 - __half2float(h0));
            __half e1 = __float2half_rn(f1 - __half2float(h1));
            __half2 hi2 = __halves2half2(h0, h1);
            __half2 lo2 = __halves2half2(e0, e1);
            *(u32*)(smem + SM_AHI + l * WPITCH + kp * 4) = *(u32*)&hi2;
            *(u32*)(smem + SM_ALO + l * WPITCH + kp * 4) = *(u32*)&lo2;
        }
        __syncthreads();

        float acc[16][4];
#pragma unroll
        for (int n = 0; n < 16; n++)
#pragma unroll
            for (int j = 0; j < 4; j++) acc[n][j] = 0.f;

        // ---- single loop: B frags once per ks; Ahi then Alo passes ----
#pragma unroll
        for (int ks = 0; ks < 8; ks++) {
            u32 bf[8][4];
#pragma unroll
            for (int nt2 = 0; nt2 < 8; nt2++) {
                int nrow = nbase + nt2 * 16 + brow0;
                ldm_x4(bf[nt2][0], bf[nt2][1], bf[nt2][2], bf[nt2][3],
                       sb + SM_W + nrow * WPITCH + (ks * 16 + bkadd) * 2);
            }
            u32 a0, a1, a2, a3;
            ldm_x4(a0, a1, a2, a3,
                   sb + SM_AHI + arow * WPITCH + (ks * 16 + akadd) * 2);
#pragma unroll
            for (int nt2 = 0; nt2 < 8; nt2++) {
                mma_f16(acc[2 * nt2],     a0, a1, a2, a3, bf[nt2][0], bf[nt2][1]);
                mma_f16(acc[2 * nt2 + 1], a0, a1, a2, a3, bf[nt2][2], bf[nt2][3]);
            }
            ldm_x4(a0, a1, a2, a3,
                   sb + SM_ALO + arow * WPITCH + (ks * 16 + akadd) * 2);
#pragma unroll
            for (int nt2 = 0; nt2 < 8; nt2++) {
                mma_f16(acc[2 * nt2],     a0, a1, a2, a3, bf[nt2][0], bf[nt2][1]);
                mma_f16(acc[2 * nt2 + 1], a0, a1, a2, a3, bf[nt2][2], bf[nt2][3]);
            }
        }
        __syncthreads();   // W region free -> zAG overlay

        // ---- scatter frags (+bias) to zAG (overlay SM_W) ----
        {
            float* zbase = (float*)(smem + SM_W) + (w >> 2) * GLT * ZPITCH;
            const float* ob = out_b + layer * 2 * H_DIM + nbase;
            int lrow = mbase + (lane >> 2);
            int ncol = 2 * (lane & 3);
#pragma unroll
            for (int nt = 0; nt < 16; nt++) {
                int n = nt * 8 + ncol;
                float b0 = __ldg(ob + n), b1 = __ldg(ob + n + 1);
                *(float2*)(zbase + lrow * ZPITCH + n) =
                    make_float2(acc[nt][0] + b0, acc[nt][1] + b1);
                *(float2*)(zbase + (lrow + 8) * ZPITCH + n) =
                    make_float2(acc[nt][2] + b0, acc[nt][3] + b1);
            }
        }
        __syncthreads();

        // ---- GLU + residual ----
        {
            int ch = tid & 127, lh = tid >> 7;
            float* zA = (float*)(smem + SM_W);
            float* zG = zA + GLT * ZPITCH;
            const float* hp = g_h + (b * H_DIM + ch) * L_SEQ + l0 + lh * 32;
            float hv[32];
#pragma unroll
            for (int i = 0; i < 8; i++) ((float4*)hv)[i] = __ldg((const float4*)hp + i);
#pragma unroll
            for (int i = 0; i < 32; i++) {
                int l = lh * 32 + i;
                float a = zA[l * ZPITCH + ch];
                float g = zG[l * ZPITCH + ch];
                zA[l * ZPITCH + ch] = fmaf(a, 1.f / (1.f + expf(-g)), hv[i]);
            }
        }
        __syncthreads();

        // ---- LayerNorm stats ----
        {
            float* zA = (float*)(smem + SM_W);
            float2* mv = (float2*)(smem + SM_MV);
#pragma unroll
            for (int l = w; l < GLT; l += 8) {
                float v0 = zA[l * ZPITCH + lane],      v1 = zA[l * ZPITCH + lane + 32];
                float v2 = zA[l * ZPITCH + lane + 64], v3 = zA[l * ZPITCH + lane + 96];
                float s = v0 + v1 + v2 + v3;
                float q = fmaf(v0, v0, fmaf(v1, v1, fmaf(v2, v2, v3 * v3)));
#pragma unroll
                for (int off = 16; off > 0; off >>= 1) {
                    s += __shfl_xor_sync(0xffffffffu, s, off);
                    q += __shfl_xor_sync(0xffffffffu, q, off);
                }
                if (lane == 0) {
                    float m   = s * (1.0f / H_DIM);
                    float var = q * (1.0f / H_DIM) - m * m;
                    mv[l] = make_float2(m, rsqrtf(var + 1e-5f));
                }
            }
        }
        __syncthreads();

        // ---- normalize + write back ----
        {
            int ch = tid & 127, lh = tid >> 7;
            float* zA = (float*)(smem + SM_W);
            float2* mv = (float2*)(smem + SM_MV);
            float gam = __ldg(ln_g + layer * H_DIM + ch);
            float bet = __ldg(ln_b + layer * H_DIM + ch);
            float r[32];
#pragma unroll
            for (int i = 0; i < 32; i++) {
                int l = lh * 32 + i;
                float2 m = mv[l];
                r[i] = fmaf((zA[l * ZPITCH + ch] - m.x) * m.y, gam, bet);
            }
            float4* wp = (float4*)(g_h + (b * H_DIM + ch) * L_SEQ + l0 + lh * 32);
#pragma unroll
            for (int i = 0; i < 8; i++) wp[i] = ((float4*)r)[i];
        }
    }
}

// ---------------- mean over L ----------------
__global__ void pool_kernel() {
    int seq = blockIdx.x;
    int t   = threadIdx.x;
    const float4* r = (const float4*)(g_h + seq * L_SEQ);
    float s = 0.f;
    for (int i = t; i < L_SEQ / 4; i += 256) {
        float4 v = r[i];
        s += v.x + v.y + v.z + v.w;
    }
    __shared__ float sm[256];
    sm[t] = s;
    __syncthreads();
    for (int off = 128; off > 0; off >>= 1) {
        if (t < off) sm[t] += sm[t + off];
        __syncthreads();
    }
    if (t == 0) g_pooled[seq] = sm[0] * (1.f / L_SEQ);
}

// ---------------- head ----------------
__global__ void head_kernel(const float* __restrict__ head_W,
                            const float* __restrict__ head_b,
                            float* __restrict__ out) {
    int t = threadIdx.x;
    if (t >= B_SZ * D_OUT) return;
    int b = t / D_OUT, o = t % D_OUT;
    float s = head_b[o];
    for (int h = 0; h < H_DIM; h++)
        s = fmaf(g_pooled[b * H_DIM + h], head_W[h * D_OUT + o], s);
    out[t] = s;
}

// ---------------- launch ----------------
extern "C" void kernel_launch(void* const* d_in, const int* in_sizes, int n_in,
                              void* d_out, int out_size) {
    const float* x          = (const float*)d_in[0];
    const float* enc_W      = (const float*)d_in[1];
    const float* enc_b      = (const float*)d_in[2];
    const float* log_dt     = (const float*)d_in[3];
    const float* C_re       = (const float*)d_in[4];
    const float* C_im       = (const float*)d_in[5];
    const float* log_A_real = (const float*)d_in[6];
    const float* A_imag     = (const float*)d_in[7];
    const float* Dvec       = (const float*)d_in[8];
    const float* out_W      = (const float*)d_in[9];
    const float* out_b      = (const float*)d_in[10];
    const float* ln_g       = (const float*)d_in[11];
    const float* ln_b       = (const float*)d_in[12];
    const float* head_W     = (const float*)d_in[13];
    const float* head_b     = (const float*)d_in[14];
    float* out = (float*)d_out;

    cudaFuncSetAttribute(glu_mma_kernel,
                         cudaFuncAttributeMaxDynamicSharedMemorySize, SMEM_MMA);

    param_kernel<<<(NL * H_DIM * NC + 127) / 128, 128>>>(log_dt, C_re, C_im,
                                                         log_A_real, A_imag);
    wsplit_kernel<<<(NL * 2 * H_DIM * H_DIM + 255) / 256, 256>>>(out_W);
    enc_kernel<<<(NSEQ * (L_SEQ / 4)) / 256, 256>>>(x, enc_W, enc_b);

    for (int layer = 0; layer < NL; layer++) {
        ssm_kernel<<<NSEQ, 64>>>(layer, Dvec);
        glu_mma_kernel<<<B_SZ * 16, 256, SMEM_MMA>>>(layer, out_b, ln_g, ln_b);
    }

    pool_kernel<<<NSEQ, 256>>>();
    head_kernel<<<1, 64>>>(head_W, head_b, out);
}

// round 15
// speedup vs baseline: 1.7092x; 1.0962x over previous
#include <cuda_runtime.h>
#include <cuda_fp16.h>
#include <math.h>

#define B_SZ   32
#define D_IN   2
#define L_SEQ  4096
#define H_DIM  128
#define NL     6
#define NC     32
#define D_OUT  2
#define NSEQ   (B_SZ * H_DIM)        // 4096
#define CHUNKS 16
#define CHLEN  (L_SEQ / CHUNKS)      // 256
#define SPT    8
#define NG     (SPT / 2)

typedef unsigned long long u64;
typedef unsigned int u32;

// ---------------- f32x2 helpers ----------------
__device__ __forceinline__ u64 pk(float lo, float hi) {
    u64 r;
    asm("mov.b64 %0, {%1, %2};" : "=l"(r) : "r"(__float_as_uint(lo)), "r"(__float_as_uint(hi)));
    return r;
}
__device__ __forceinline__ void upk(u64 a, float& lo, float& hi) {
    u32 x, y;
    asm("mov.b64 {%0, %1}, %2;" : "=r"(x), "=r"(y) : "l"(a));
    lo = __uint_as_float(x); hi = __uint_as_float(y);
}
__device__ __forceinline__ u64 fma2(u64 a, u64 b, u64 c) {
    u64 d;
    asm("fma.rn.f32x2 %0, %1, %2, %3;" : "=l"(d) : "l"(a), "l"(b), "l"(c));
    return d;
}
__device__ __forceinline__ u64 mul2(u64 a, u64 b) {
    u64 d;
    asm("mul.rn.f32x2 %0, %1, %2;" : "=l"(d) : "l"(a), "l"(b));
    return d;
}

// ---------------- tensor-core helpers (baseline sm_103 ISA) ----------------
__device__ __forceinline__ unsigned smaddr(const void* p) {
    unsigned a;
    asm("{ .reg .u64 t; cvta.to.shared.u64 t, %1; cvt.u32.u64 %0, t; }" : "=r"(a) : "l"(p));
    return a;
}
__device__ __forceinline__ void ldm_x4(u32& r0, u32& r1, u32& r2, u32& r3, unsigned addr) {
    asm volatile("ldmatrix.sync.aligned.m8n8.x4.shared.b16 {%0,%1,%2,%3}, [%4];"
                 : "=r"(r0), "=r"(r1), "=r"(r2), "=r"(r3) : "r"(addr));
}
__device__ __forceinline__ void mma_f16(float* c, u32 a0, u32 a1, u32 a2, u32 a3,
                                        u32 b0, u32 b1) {
    asm volatile(
        "mma.sync.aligned.m16n8k16.row.col.f32.f16.f16.f32 "
        "{%0,%1,%2,%3}, {%4,%5,%6,%7}, {%8,%9}, {%0,%1,%2,%3};"
        : "+f"(c[0]), "+f"(c[1]), "+f"(c[2]), "+f"(c[3])
        : "r"(a0), "r"(a1), "r"(a2), "r"(a3), "r"(b0), "r"(b1));
}

// smem layout for glu_mma (dynamic). Pitch 272B -> conflict-free ldmatrix.
#define WPITCH 272
#define SM_W   0                    // 256 x 272 = 69632 (Wf16; zAG overlay)
#define SM_A   69632                // 64 x 272 = 17408 (y fp16)
#define SM_MV  87040                // 64 x float2
#define SMEM_MMA 87552
#define ZPITCH 132                  // floats (zAG overlay on SM_W)

#define GLT 64
#define TILES_PER_BLK 4

// ---------------- scratch ----------------
__device__ float  g_h[NSEQ * L_SEQ];
__device__ float  g_y[NSEQ * L_SEQ];
__device__ float  g_par[NL * 6 * H_DIM * NC];        // wre,wim,c2re,c2im,wpre,wpim
__device__ __half g_Wf[NL * 2 * H_DIM * H_DIM];      // fp16 weights
__device__ float  g_pooled[NSEQ];

// ---------------- parameter precompute (double; complex form) ----------------
__global__ void param_kernel(const float* __restrict__ log_dt,
                             const float* __restrict__ C_re,
                             const float* __restrict__ C_im,
                             const float* __restrict__ log_A_real,
                             const float* __restrict__ A_imag) {
    int t = blockIdx.x * blockDim.x + threadIdx.x;
    if (t >= NL * H_DIM * NC) return;
    int layer = t / (H_DIM * NC);
    int hn    = t % (H_DIM * NC);
    int h     = hn / NC;

    double dt  = exp((double)log_dt[layer * H_DIM + h]);
    double Are = -exp((double)log_A_real[t]);
    double Aim = (double)A_imag[t];
    double xre = Are * dt, xim = Aim * dt;

    double ex = exp(xre);
    double sy, cy;
    sincos(xim, &sy, &cy);
    double wre = ex * cy, wim = ex * sy;

    double em1re = ex * cy - 1.0;
    double em1im = ex * sy;

    double den = Are * Are + Aim * Aim;
    double fre = (em1re * Are + em1im * Aim) / den;
    double fim = (em1im * Are - em1re * Aim) / den;
    double cre = (double)C_re[t], cim = (double)C_im[t];
    double c2re = 2.0 * (cre * fre - cim * fim);
    double c2im = 2.0 * (cre * fim + cim * fre);

    double pre = exp(xre * (double)CHLEN);
    double ps, pc;
    sincos(xim * (double)CHLEN, &ps, &pc);

    int S = H_DIM * NC;
    int base = layer * 6 * S + hn;
    g_par[base]         = (float)wre;
    g_par[base + S]     = (float)wim;
    g_par[base + 2 * S] = (float)c2re;
    g_par[base + 3 * S] = (float)c2im;
    g_par[base + 4 * S] = (float)(pre * pc);
    g_par[base + 5 * S] = (float)(pre * ps);
}

// ---------------- weight fp16 convert ----------------
__global__ void wsplit_kernel(const float* __restrict__ out_W) {
    int t = blockIdx.x * blockDim.x + threadIdx.x;
    if (t >= NL * 2 * H_DIM * H_DIM) return;
    g_Wf[t] = __float2half_rn(out_W[t]);
}

// ---------------- encoder ----------------
__global__ void enc_kernel(const float* __restrict__ x,
                           const float* __restrict__ enc_W,
                           const float* __restrict__ enc_b) {
    int t = blockIdx.x * blockDim.x + threadIdx.x;
    if (t >= NSEQ * (L_SEQ / 4)) return;
    int l4  = t % (L_SEQ / 4);
    int seq = t / (L_SEQ / 4);
    int b = seq / H_DIM;
    int h = seq % H_DIM;
    float w0 = enc_W[h];
    float w1 = enc_W[H_DIM + h];
    float bb = enc_b[h];
    float4 a = ((const float4*)(x + (b * D_IN + 0) * L_SEQ))[l4];
    float4 c = ((const float4*)(x + (b * D_IN + 1) * L_SEQ))[l4];
    float4 r;
    r.x = fmaf(w1, c.x, fmaf(w0, a.x, bb));
    r.y = fmaf(w1, c.y, fmaf(w0, a.y, bb));
    r.z = fmaf(w1, c.z, fmaf(w0, a.z, bb));
    r.w = fmaf(w1, c.w, fmaf(w0, a.w, bb));
    ((float4*)(g_h + seq * L_SEQ))[l4] = r;
}

// ===== fused SSM: pass1 (chunk states -> smem E) + pass2 (full recurrence) =====
__global__ void __launch_bounds__(64) ssm_kernel(int layer,
                                                 const float* __restrict__ Dvec) {
    __shared__ float2 E[CHUNKS][NC];

    int t = threadIdx.x;
    int quarter = t & 3;
    int chunk   = t >> 2;
    int seq = blockIdx.x;
    int h = seq % H_DIM;

    const float* par = g_par + layer * 6 * H_DIM * NC;
    int S  = H_DIM * NC;
    int pb = h * NC + quarter * SPT;

    u64 wre2[NG], wim2[NG], nwim2[NG], sre2[NG], sim2[NG];
#pragma unroll
    for (int g = 0; g < NG; g++) {
        float2 wr = *(const float2*)(par + pb + 2 * g);
        float2 wi = *(const float2*)(par + S + pb + 2 * g);
        wre2[g]  = pk(wr.x, wr.y);
        wim2[g]  = pk(wi.x, wi.y);
        nwim2[g] = pk(-wi.x, -wi.y);
        sre2[g] = 0ull; sim2[g] = 0ull;
    }

    const float4* u4 = (const float4*)(g_h + seq * L_SEQ + chunk * CHLEN);
    for (int l = 0; l < CHLEN / 4; l++) {
        float4 u = u4[l];
        float uu[4] = {u.x, u.y, u.z, u.w};
#pragma unroll
        for (int q = 0; q < 4; q++) {
            u64 u2 = pk(uu[q], uu[q]);
#pragma unroll
            for (int g = 0; g < NG; g++) {
                u64 nr = fma2(nwim2[g], sim2[g], fma2(wre2[g], sre2[g], u2));
                u64 ni = fma2(wre2[g], sim2[g], mul2(wim2[g], sre2[g]));
                sre2[g] = nr; sim2[g] = ni;
            }
        }
    }
#pragma unroll
    for (int g = 0; g < NG; g++) {
        float r0, r1, i0, i1;
        upk(sre2[g], r0, r1);
        upk(sim2[g], i0, i1);
        E[chunk][quarter * SPT + 2 * g]     = make_float2(r0, i0);
        E[chunk][quarter * SPT + 2 * g + 1] = make_float2(r1, i1);
    }
    __syncthreads();

#pragma unroll
    for (int g = 0; g < NG; g++) { sre2[g] = 0ull; sim2[g] = 0ull; }

    if (chunk > 0) {
        u64 wpre2[NG], wpim2[NG], nwpim2[NG];
#pragma unroll
        for (int g = 0; g < NG; g++) {
            float2 wr = *(const float2*)(par + 4 * S + pb + 2 * g);
            float2 wi = *(const float2*)(par + 5 * S + pb + 2 * g);
            wpre2[g]  = pk(wr.x, wr.y);
            wpim2[g]  = pk(wi.x, wi.y);
            nwpim2[g] = pk(-wi.x, -wi.y);
        }
        for (int c = 0; c < chunk; c++) {
            const float2* Ec = &E[c][quarter * SPT];
#pragma unroll
            for (int g = 0; g < NG; g++) {
                float2 e0 = Ec[2 * g], e1 = Ec[2 * g + 1];
                u64 re2 = pk(e0.x, e1.x);
                u64 im2 = pk(e0.y, e1.y);
                u64 nr = fma2(wpre2[g], sre2[g], fma2(nwpim2[g], sim2[g], re2));
                u64 ni = fma2(wpre2[g], sim2[g], fma2(wpim2[g], sre2[g], im2));
                sre2[g] = nr; sim2[g] = ni;
            }
        }
    }

    u64 cr2[NG], nci2[NG];
#pragma unroll
    for (int g = 0; g < NG; g++) {
        float2 cr = *(const float2*)(par + 2 * S + pb + 2 * g);
        float2 ci = *(const float2*)(par + 3 * S + pb + 2 * g);
        cr2[g]  = pk(cr.x, cr.y);
        nci2[g] = pk(-ci.x, -ci.y);
    }
    float Dh = Dvec[layer * H_DIM + h];

    float* yp = g_y + seq * L_SEQ + chunk * CHLEN;

    int  q1 = quarter & 1;
    bool q2 = (quarter & 2) != 0;

    for (int l = 0; l < CHLEN / 4; l++) {
        float4 u = u4[l];
        float uu[4] = {u.x, u.y, u.z, u.w};
        float s[4];
#pragma unroll
        for (int q = 0; q < 4; q++) {
            float uv = uu[q];
            u64 u2 = pk(uv, uv);
            u64 acc2 = 0ull;
#pragma unroll
            for (int g = 0; g < NG; g++) {
                u64 nr = fma2(nwim2[g], sim2[g], fma2(wre2[g], sre2[g], u2));
                u64 ni = fma2(wre2[g], sim2[g], mul2(wim2[g], sre2[g]));
                sre2[g] = nr; sim2[g] = ni;
                acc2 = fma2(cr2[g], nr, acc2);
                acc2 = fma2(nci2[g], ni, acc2);
            }
            float alo, ahi;
            upk(acc2, alo, ahi);
            s[q] = alo + ahi;
        }
        float sA = q1 ? s[1] : s[0];
        float sB = q1 ? s[0] : s[1];
        float sC = q1 ? s[3] : s[2];
        float sD = q1 ? s[2] : s[3];
        float p0 = sA + __shfl_xor_sync(0xffffffffu, sB, 1);
        float p1 = sC + __shfl_xor_sync(0xffffffffu, sD, 1);
        float send2 = q2 ? p0 : p1;
        float tot = (q2 ? p1 : p0) + __shfl_xor_sync(0xffffffffu, send2, 2);
        float ua = q1 ? uu[1] : uu[0];
        float ub = q1 ? uu[3] : uu[2];
        float um = q2 ? ub : ua;
        float yv = fmaf(um, Dh, tot);
        float gl = 0.5f * yv * (1.f + erff(yv * 0.7071067811865476f));
        yp[4 * l + quarter] = gl;
    }
}

// ====== GLU via mma.sync fp16 SINGLE pass + fused GLU/residual/LN ======
__global__ void __launch_bounds__(256, 2) glu_mma_kernel(int layer,
                           const float* __restrict__ out_b,
                           const float* __restrict__ ln_g,
                           const float* __restrict__ ln_b) {
    extern __shared__ char smem[];
    unsigned sb = smaddr(smem);
    int tid = threadIdx.x;
    int w = tid >> 5, lane = tid & 31;

    int b   = blockIdx.x >> 4;
    int seg = blockIdx.x & 15;

    int mbase = (w & 3) * 16;
    int nbase = (w >> 2) * 128;
    int sel   = lane >> 3;
    int arow  = mbase + (lane & 7) + (sel & 1) * 8;
    int akadd = (sel >> 1) * 8;
    int brow0 = (lane & 7) + (sel >> 1) * 8;
    int bkadd = (sel & 1) * 8;

    const uint4* wf_g = (const uint4*)(g_Wf + layer * 2 * H_DIM * H_DIM);

    for (int tl = 0; tl < TILES_PER_BLK; tl++) {
        int l0 = seg * 256 + tl * 64;
        __syncthreads();   // previous tile's epilogue done (zAG overlay freed)

        // ---- stage Wf16 + Y fp16 ----
#pragma unroll
        for (int it = 0; it < 16; it++) {
            int idx = tid + it * 256;
            int o = idx >> 4, c = idx & 15;
            *(uint4*)(smem + SM_W + o * WPITCH + c * 16) = __ldg(wf_g + idx);
        }
#pragma unroll
        for (int it = 0; it < 16; it++) {
            int idx = tid + it * 256;
            int l = idx & 63, kp = idx >> 6;
            const float* r0 = g_y + (b * H_DIM + 2 * kp) * L_SEQ + l0;
            const float* r1 = r0 + L_SEQ;
            float f0 = __ldg(r0 + l);
            float f1 = __ldg(r1 + l);
            __half2 hi2 = __halves2half2(__float2half_rn(f0), __float2half_rn(f1));
            *(u32*)(smem + SM_A + l * WPITCH + kp * 4) = *(u32*)&hi2;
        }
        __syncthreads();

        float acc[16][4];
#pragma unroll
        for (int n = 0; n < 16; n++)
#pragma unroll
            for (int j = 0; j < 4; j++) acc[n][j] = 0.f;

        // ---- single pass: A x W ----
#pragma unroll
        for (int ks = 0; ks < 8; ks++) {
            u32 a0, a1, a2, a3;
            ldm_x4(a0, a1, a2, a3,
                   sb + SM_A + arow * WPITCH + (ks * 16 + akadd) * 2);
#pragma unroll
            for (int nt2 = 0; nt2 < 8; nt2++) {
                u32 b0, b1, b2, b3;
                int nrow = nbase + nt2 * 16 + brow0;
                ldm_x4(b0, b1, b2, b3,
                       sb + SM_W + nrow * WPITCH + (ks * 16 + bkadd) * 2);
                mma_f16(acc[2 * nt2],     a0, a1, a2, a3, b0, b1);
                mma_f16(acc[2 * nt2 + 1], a0, a1, a2, a3, b2, b3);
            }
        }
        __syncthreads();   // W region free -> zAG overlay

        // ---- scatter frags (+bias) to zAG (overlay SM_W) ----
        {
            float* zbase = (float*)(smem + SM_W) + (w >> 2) * GLT * ZPITCH;
            const float* ob = out_b + layer * 2 * H_DIM + nbase;
            int lrow = mbase + (lane >> 2);
            int ncol = 2 * (lane & 3);
#pragma unroll
            for (int nt = 0; nt < 16; nt++) {
                int n = nt * 8 + ncol;
                float b0 = __ldg(ob + n), b1 = __ldg(ob + n + 1);
                *(float2*)(zbase + lrow * ZPITCH + n) =
                    make_float2(acc[nt][0] + b0, acc[nt][1] + b1);
                *(float2*)(zbase + (lrow + 8) * ZPITCH + n) =
                    make_float2(acc[nt][2] + b0, acc[nt][3] + b1);
            }
        }
        __syncthreads();

        // ---- GLU + residual ----
        {
            int ch = tid & 127, lh = tid >> 7;
            float* zA = (float*)(smem + SM_W);
            float* zG = zA + GLT * ZPITCH;
            const float* hp = g_h + (b * H_DIM + ch) * L_SEQ + l0 + lh * 32;
            float hv[32];
#pragma unroll
            for (int i = 0; i < 8; i++) ((float4*)hv)[i] = __ldg((const float4*)hp + i);
#pragma unroll
            for (int i = 0; i < 32; i++) {
                int l = lh * 32 + i;
                float a = zA[l * ZPITCH + ch];
                float g = zG[l * ZPITCH + ch];
                zA[l * ZPITCH + ch] = fmaf(a, 1.f / (1.f + expf(-g)), hv[i]);
            }
        }
        __syncthreads();

        // ---- LayerNorm stats ----
        {
            float* zA = (float*)(smem + SM_W);
            float2* mv = (float2*)(smem + SM_MV);
#pragma unroll
            for (int l = w; l < GLT; l += 8) {
                float v0 = zA[l * ZPITCH + lane],      v1 = zA[l * ZPITCH + lane + 32];
                float v2 = zA[l * ZPITCH + lane + 64], v3 = zA[l * ZPITCH + lane + 96];
                float s = v0 + v1 + v2 + v3;
                float q = fmaf(v0, v0, fmaf(v1, v1, fmaf(v2, v2, v3 * v3)));
#pragma unroll
                for (int off = 16; off > 0; off >>= 1) {
                    s += __shfl_xor_sync(0xffffffffu, s, off);
                    q += __shfl_xor_sync(0xffffffffu, q, off);
                }
                if (lane == 0) {
                    float m   = s * (1.0f / H_DIM);
                    float var = q * (1.0f / H_DIM) - m * m;
                    mv[l] = make_float2(m, rsqrtf(var + 1e-5f));
                }
            }
        }
        __syncthreads();

        // ---- normalize + write back ----
        {
            int ch = tid & 127, lh = tid >> 7;
            float* zA = (float*)(smem + SM_W);
            float2* mv = (float2*)(smem + SM_MV);
            float gam = __ldg(ln_g + layer * H_DIM + ch);
            float bet = __ldg(ln_b + layer * H_DIM + ch);
            float r[32];
#pragma unroll
            for (int i = 0; i < 32; i++) {
                int l = lh * 32 + i;
                float2 m = mv[l];
                r[i] = fmaf((zA[l * ZPITCH + ch] - m.x) * m.y, gam, bet);
            }
            float4* wp = (float4*)(g_h + (b * H_DIM + ch) * L_SEQ + l0 + lh * 32);
#pragma unroll
            for (int i = 0; i < 8; i++) wp[i] = ((float4*)r)[i];
        }
    }
}

// ---------------- mean over L ----------------
__global__ void pool_kernel() {
    int seq = blockIdx.x;
    int t   = threadIdx.x;
    const float4* r = (const float4*)(g_h + seq * L_SEQ);
    float s = 0.f;
    for (int i = t; i < L_SEQ / 4; i += 256) {
        float4 v = r[i];
        s += v.x + v.y + v.z + v.w;
    }
    __shared__ float sm[256];
    sm[t] = s;
    __syncthreads();
    for (int off = 128; off > 0; off >>= 1) {
        if (t < off) sm[t] += sm[t + off];
        __syncthreads();
    }
    if (t == 0) g_pooled[seq] = sm[0] * (1.f / L_SEQ);
}

// ---------------- head ----------------
__global__ void head_kernel(const float* __restrict__ head_W,
                            const float* __restrict__ head_b,
                            float* __restrict__ out) {
    int t = threadIdx.x;
    if (t >= B_SZ * D_OUT) return;
    int b = t / D_OUT, o = t % D_OUT;
    float s = head_b[o];
    for (int h = 0; h < H_DIM; h++)
        s = fmaf(g_pooled[b * H_DIM + h], head_W[h * D_OUT + o], s);
    out[t] = s;
}

// ---------------- launch ----------------
extern "C" void kernel_launch(void* const* d_in, const int* in_sizes, int n_in,
                              void* d_out, int out_size) {
    const float* x          = (const float*)d_in[0];
    const float* enc_W      = (const float*)d_in[1];
    const float* enc_b      = (const float*)d_in[2];
    const float* log_dt     = (const float*)d_in[3];
    const float* C_re       = (const float*)d_in[4];
    const float* C_im       = (const float*)d_in[5];
    const float* log_A_real = (const float*)d_in[6];
    const float* A_imag     = (const float*)d_in[7];
    const float* Dvec       = (const float*)d_in[8];
    const float* out_W      = (const float*)d_in[9];
    const float* out_b      = (const float*)d_in[10];
    const float* ln_g       = (const float*)d_in[11];
    const float* ln_b       = (const float*)d_in[12];
    const float* head_W     = (const float*)d_in[13];
    const float* head_b     = (const float*)d_in[14];
    float* out = (float*)d_out;

    cudaFuncSetAttribute(glu_mma_kernel,
                         cudaFuncAttributeMaxDynamicSharedMemorySize, SMEM_MMA);

    param_kernel<<<(NL * H_DIM * NC + 127) / 128, 128>>>(log_dt, C_re, C_im,
                                                         log_A_real, A_imag);
    wsplit_kernel<<<(NL * 2 * H_DIM * H_DIM + 255) / 256, 256>>>(out_W);
    enc_kernel<<<(NSEQ * (L_SEQ / 4)) / 256, 256>>>(x, enc_W, enc_b);

    for (int layer = 0; layer < NL; layer++) {
        ssm_kernel<<<NSEQ, 64>>>(layer, Dvec);
        glu_mma_kernel<<<B_SZ * 16, 256, SMEM_MMA>>>(layer, out_b, ln_g, ln_b);
    }

    pool_kernel<<<NSEQ, 256>>>();
    head_kernel<<<1, 64>>>(head_W, head_b, out);
}